// round 15
// baseline (speedup 1.0000x reference)
#include <cuda_runtime.h>
#include <math.h>

#define BB 4
#define LL 5
#define TT 10
#define CC 64
#define HH 100
#define WW 352
#define NN (BB*LL)
#define HW (HH*WW)
#define H4 25
#define W4 88
#define P4 (H4*W4)

// PDL: let dependents launch early; wait = predecessor grid fully complete + visible
#define PDL_TRIGGER() asm volatile("griddepcontrol.launch_dependents;" ::: "memory")
#define PDL_WAIT()    asm volatile("griddepcontrol.wait;" ::: "memory")

// scratch (no allocations allowed)
__device__ float g_tm4[NN*P4];
__device__ float g_has[NN];
__device__ float g_f[NN*128];
__device__ float g_R[9*128*64];       // conv weights pre-reduced to 9 border cases
__device__ int   g_xi[NN*TT], g_yi[NN*TT];

// fast sigmoid via tanh.approx (mask path only -- feeds a 0.01 threshold, never the output values)
__device__ __forceinline__ float fast_sigmoid(float xv) {
    float t;
    asm("tanh.approx.f32 %0, %1;" : "=f"(t) : "f"(xv*0.5f));
    return fmaf(t, 0.5f, 0.5f);
}

// 5x5 gaussian, sigma=1, scaled by 1/(2*pi*sigma)
__constant__ float c_G[25] = {
    0.0029150244947655228f, 0.013064233284684921f, 0.021539279301848634f, 0.013064233284684921f, 0.0029150244947655228f,
    0.013064233284684921f, 0.05854983152431917f, 0.09653235263005391f, 0.05854983152431917f, 0.013064233284684921f,
    0.021539279301848634f, 0.09653235263005391f, 0.15915494309189535f, 0.09653235263005391f, 0.021539279301848634f,
    0.013064233284684921f, 0.05854983152431917f, 0.09653235263005391f, 0.05854983152431917f, 0.013064233284684921f,
    0.0029150244947655228f, 0.013064233284684921f, 0.021539279301848634f, 0.013064233284684921f, 0.0029150244947655228f
};

// 7x7 splat table: exp(-(di^2+dj^2)/8), di,dj in [-3,3]
__constant__ float c_g7[49] = {
    0.10539922456186433f, 0.19689917292530676f, 0.2865047968601901f, 0.32465246735834974f, 0.2865047968601901f, 0.19689917292530676f, 0.10539922456186433f,
    0.19689917292530676f, 0.36787944117144233f, 0.5352614285189903f, 0.6065306597126334f, 0.5352614285189903f, 0.36787944117144233f, 0.19689917292530676f,
    0.2865047968601901f, 0.5352614285189903f, 0.7788007830714049f, 0.8824969025845955f, 0.7788007830714049f, 0.5352614285189903f, 0.2865047968601901f,
    0.32465246735834974f, 0.6065306597126334f, 0.8824969025845955f, 1.0f, 0.8824969025845955f, 0.6065306597126334f, 0.32465246735834974f,
    0.2865047968601901f, 0.5352614285189903f, 0.7788007830714049f, 0.8824969025845955f, 0.7788007830714049f, 0.5352614285189903f, 0.2865047968601901f,
    0.19689917292530676f, 0.36787944117144233f, 0.5352614285189903f, 0.6065306597126334f, 0.5352614285189903f, 0.36787944117144233f, 0.19689917292530676f,
    0.10539922456186433f, 0.19689917292530676f, 0.2865047968601901f, 0.32465246735834974f, 0.2865047968601901f, 0.19689917292530676f, 0.10539922456186433f
};

// ---------------- K1: prep. Blocks 0..127: reduce Wc1 -> R. Blocks 128..147: per-agent MLP ----------------
__global__ void __launch_bounds__(128)
k_prep(const float* __restrict__ traj_all,
       const float* __restrict__ W1, const float* __restrict__ b1,
       const float* __restrict__ W2, const float* __restrict__ b2,
       const float* __restrict__ Wc1)
{
    PDL_TRIGGER();
    int bid = blockIdx.x;
    int tid = threadIdx.x;

    if (bid < 128) {
        if (tid < 64) {
            int k = bid, o = tid;
            const float* w = Wc1 + (size_t)o*1152 + k*9;
            float w00=w[0], w01=w[1], w02=w[2];
            float w10=w[3], w11=w[4], w12=w[5];
            float w20=w[6], w21=w[7], w22=w[8];
            float rF0=w00+w01+w02, rL0=w01+w02, rR0=w00+w01;
            float rF1=w10+w11+w12, rL1=w11+w12, rR1=w10+w11;
            float rF2=w20+w21+w22, rL2=w21+w22, rR2=w20+w21;
            g_R[(0*128+k)*64+o]=rL1+rL2; g_R[(1*128+k)*64+o]=rF1+rF2; g_R[(2*128+k)*64+o]=rR1+rR2;
            g_R[(3*128+k)*64+o]=rL0+rL1+rL2; g_R[(4*128+k)*64+o]=rF0+rF1+rF2; g_R[(5*128+k)*64+o]=rR0+rR1+rR2;
            g_R[(6*128+k)*64+o]=rL0+rL1; g_R[(7*128+k)*64+o]=rF0+rF1; g_R[(8*128+k)*64+o]=rR0+rR1;
        }
        return;
    }

    int n = bid - 128;
    __shared__ float s_tr[TT*3];
    __shared__ float s_h[64];
    if (tid < TT*3) s_tr[tid] = traj_all[n*TT*3 + tid];
    __syncthreads();

    if (tid == 0) {
        int h = 0;
        for (int i = 0; i < TT*3; i++) if (s_tr[i] != 0.0f) h = 1;
        g_has[n] = (float)h;
    }
    if (tid < TT) {
        float px = s_tr[tid*3+0] / 0.4f;     // DISCRETE_RATIO
        float py = s_tr[tid*3+1] / 0.4f;
        int xi = (int)(px / 4.0f);           // truncation like .astype(int32)
        int yi = (int)(py / 4.0f);
        g_xi[n*TT+tid] = min(max(xi, 0), W4-1);
        g_yi[n*TT+tid] = min(max(yi, 0), H4-1);
    }
    if (tid < 64) {
        float acc = 0.0f;
        #pragma unroll
        for (int t = 0; t < TT; t++) {
            float z = b1[tid];
            z += s_tr[t*3+0]*W1[0*64+tid];
            z += s_tr[t*3+1]*W1[1*64+tid];
            z += s_tr[t*3+2]*W1[2*64+tid];
            acc += fmaxf(z, 0.0f);
        }
        s_h[tid] = acc * 0.1f;
    }
    __syncthreads();
    {
        float z = b2[tid];
        #pragma unroll 8
        for (int c = 0; c < 64; c++) z += s_h[c]*W2[c*128+tid];
        g_f[n*128+tid] = z;
    }
}

// ---------------- K2: per-agent attention(9 cases) + table splat + normalize ----------------
__global__ void __launch_bounds__(576)
k_traj2(const float* __restrict__ bc1, const float* __restrict__ Wc2,
        const float* __restrict__ bc2)
{
    PDL_TRIGGER();
    int n = blockIdx.x;
    int tid = threadIdx.x;
    __shared__ float s_f[128];
    __shared__ float s_a9[9];
    __shared__ float s_red[9][2];
    __shared__ int   s_xi[TT], s_yi[TT];
    __shared__ float s_g7[49];
    __shared__ float s_m[P4];
    __shared__ float s_wsum[18];

    if (tid >= 128 && tid < 128+49) s_g7[tid-128] = c_g7[tid-128];  // independent prelude
    PDL_WAIT();   // g_f/g_xi/g_R ready
    if (tid < 128) s_f[tid] = g_f[n*128+tid];
    if (tid < TT) { s_xi[tid] = g_xi[n*TT+tid]; s_yi[tid] = g_yi[n*TT+tid]; }
    __syncthreads();

    {
        int q = tid / 64, o = tid & 63;
        float acc = bc1[o];
        const float* Rp = g_R + (size_t)q*128*64 + o;
        #pragma unroll 8
        for (int k = 0; k < 128; k++) acc += s_f[k] * Rp[(size_t)k*64];
        float t = Wc2[o] * fmaxf(acc, 0.0f);
        #pragma unroll
        for (int off = 16; off > 0; off >>= 1)
            t += __shfl_down_sync(0xFFFFFFFFu, t, off);
        if ((tid & 31) == 0) s_red[q][(tid >> 5) & 1] = t;
    }
    __syncthreads();
    if (tid < 9) {
        float z = bc2[0] + s_red[tid][0] + s_red[tid][1];
        s_a9[tid] = fast_sigmoid(z);
    }
    __syncthreads();

    float lsum = 0.0f;
    for (int p = tid; p < P4; p += 576) {
        int i = p / W4, j = p - (p / W4)*W4;
        float m = 0.0f;
        #pragma unroll
        for (int t = 0; t < TT; t++) {
            int di = i - s_yi[t] + 3, dj = j - s_xi[t] + 3;
            if ((unsigned)di < 7u && (unsigned)dj < 7u) m += s_g7[di*7+dj];
        }
        s_m[p] = m; lsum += m;
    }
    #pragma unroll
    for (int off = 16; off > 0; off >>= 1)
        lsum += __shfl_down_sync(0xFFFFFFFFu, lsum, off);
    if ((tid & 31) == 0) s_wsum[tid >> 5] = lsum;
    __syncthreads();
    if (tid == 0) {
        float t = 0.0f;
        #pragma unroll
        for (int w = 0; w < 18; w++) t += s_wsum[w];
        s_wsum[0] = 1.0f / fmaxf(t, 1e-12f);
    }
    __syncthreads();
    float inv = s_wsum[0];
    for (int p = tid; p < P4; p += 576) {
        int i = p / W4, j = p - (p / W4)*W4;
        int r  = (i == 0) ? 0 : ((i == H4-1) ? 2 : 1);
        int cc = (j == 0) ? 0 : ((j == W4-1) ? 2 : 1);
        g_tm4[n*P4 + p] = s_m[p]*inv*s_a9[r*3+cc];
    }
}

// ---------------- K3: fusion with INLINE mask (cmask kernel deleted) ----------------
// Block = 32 px (one row segment; 352%32==0 so no row straddle) x 8 channel-groups.
// Phase 1 (traj-independent): x loads + raw ego dots + psm halo [5ag][5rows][36cols] -> smem.
// Phase 2 (after PDL_WAIT on traj2): cmap = sigmoid(psm*fac) max over A, 5x5 gaussian conv,
// threshold -> mask; softmax; output. g_tm4 is 176KB -> L1/L2 resident.
__global__ void __launch_bounds__(256)
k_fuse(const float* __restrict__ x, const float* __restrict__ psm,
       float* __restrict__ out)
{
    __shared__ float s_d[8][5][32];
    __shared__ float s_p0[900];       // [m][r][c] flat: m*180 + r*36 + c
    __shared__ float s_p1[900];
    __shared__ float s_cm[900];
    __shared__ float s_mk[5][32];

    int px = threadIdx.x & 31;
    int cg = threadIdx.x >> 5;        // 0..7
    int pbase = blockIdx.x * 32;
    int p  = pbase + px;              // HW = 35200 = 1100 * 32
    int b  = blockIdx.y;
    int py   = pbase / WW;            // whole block in one row
    int col0 = pbase - py*WW;

    const float* xb = x + (size_t)b*LL*CC*HW + p;

    // ---- phase 1a: psm halo -> smem (no traj dependency) ----
    for (int i = threadIdx.x; i < 900; i += 256) {
        int m = i / 180, rem = i - m*180;
        int r = rem / 36, c = rem - r*36;
        int gy = py - 2 + r, gx = col0 - 2 + c;
        float a0 = 0.0f, a1 = 0.0f;
        if ((unsigned)gy < (unsigned)HH && (unsigned)gx < (unsigned)WW) {
            size_t off = (size_t)((b*LL + m)*2)*HW + gy*WW + gx;
            a0 = psm[off]; a1 = psm[off + HW];
        }
        s_p0[i] = a0; s_p1[i] = a1;
    }

    // ---- phase 1b: raw x loads + raw ego dots ----
    float v[LL][8];
    #pragma unroll
    for (int m = 0; m < LL; m++) {
        #pragma unroll
        for (int i = 0; i < 8; i++)
            v[m][i] = xb[(size_t)(m*CC + cg*8 + i)*HW];
    }
    float d[LL];
    #pragma unroll
    for (int m = 0; m < LL; m++) d[m] = 0.0f;
    #pragma unroll
    for (int i = 0; i < 8; i++) {
        #pragma unroll
        for (int m = 0; m < LL; m++) d[m] += v[0][i]*v[m][i];
    }
    #pragma unroll
    for (int m = 0; m < LL; m++) s_d[cg][m][px] = d[m];
    __syncthreads();          // covers s_d and s_p0/s_p1

    // ---- phase 2: traj chain products needed now ----
    PDL_WAIT();

    for (int i = threadIdx.x; i < 900; i += 256) {
        int m = i / 180, rem = i - m*180;
        int r = rem / 36, c = rem - r*36;
        int gy = py - 2 + r, gx = col0 - 2 + c;
        float val = 0.0f;
        if ((unsigned)gy < (unsigned)HH && (unsigned)gx < (unsigned)WW) {
            int n = b*LL + m;
            const float* tmn = g_tm4 + n*P4;
            float uy = fminf(fmaxf((gy+0.5f)*0.25f - 0.5f, 0.0f), (float)(H4-1));
            float ux = fminf(fmaxf((gx+0.5f)*0.25f - 0.5f, 0.0f), (float)(W4-1));
            int y0 = (int)uy, x0 = (int)ux;
            float fy = uy - y0, fx = ux - x0;
            int y1 = min(y0+1, H4-1), x1 = min(x0+1, W4-1);
            float v00 = tmn[y0*W4+x0], v01 = tmn[y0*W4+x1];
            float v10 = tmn[y1*W4+x0], v11 = tmn[y1*W4+x1];
            float tm = v00*(1.0f-fy)*(1.0f-fx) + v01*(1.0f-fy)*fx
                     + v10*fy*(1.0f-fx)        + v11*fy*fx;
            float fac = 1.0f + g_has[n]*tm;
            float c0 = fast_sigmoid(s_p0[i]*fac);
            float c1 = fast_sigmoid(s_p1[i]*fac);
            val = fmaxf(c0, c1);
        }
        s_cm[i] = val;
    }
    __syncthreads();

    // 5 warps: 25-tap gaussian conv + threshold for their agent
    if (cg < LL) {
        const float* cmm = s_cm + cg*180;
        float acc = 0.0f;
        #pragma unroll
        for (int dy = 0; dy < 5; dy++) {
            #pragma unroll
            for (int dx = 0; dx < 5; dx++)
                acc += c_G[dy*5+dx] * cmm[dy*36 + px + dx];
        }
        s_mk[cg][px] = (cg == 0) ? 1.0f : ((acc > 0.01f) ? 1.0f : 0.0f);
    }
    __syncthreads();

    float mk[LL];
    #pragma unroll
    for (int m = 0; m < LL; m++) mk[m] = s_mk[m][px];

    float e[LL], sum = 0.0f;
    #pragma unroll
    for (int m = 0; m < LL; m++) {
        float acc = 0.0f;
        #pragma unroll
        for (int g = 0; g < 8; g++) acc += s_d[g][m][px];
        e[m] = __expf(acc * mk[m] * 0.125f);   // mk in {0,1}, mk[0]==1; bounded exponent
        sum += e[m];
    }
    float isum = 1.0f/sum;

    float* ob = out + (size_t)b*CC*HW + p;
    #pragma unroll
    for (int i = 0; i < 8; i++) {
        float acc = e[0]*v[0][i]*mk[0] + e[1]*v[1][i]*mk[1] + e[2]*v[2][i]*mk[2]
                  + e[3]*v[3][i]*mk[3] + e[4]*v[4][i]*mk[4];
        ob[(size_t)(cg*8+i)*HW] = acc * isum;
    }
}

extern "C" void kernel_launch(void* const* d_in, const int* in_sizes, int n_in,
                              void* d_out, int out_size)
{
    const float* x    = (const float*)d_in[0];
    const float* psm  = (const float*)d_in[1];
    // d_in[2] record_len, d_in[3] pairwise_t_matrix: unused by reference
    const float* traj = (const float*)d_in[4];
    const float* W1   = (const float*)d_in[5];
    const float* b1   = (const float*)d_in[6];
    const float* W2   = (const float*)d_in[7];
    const float* b2   = (const float*)d_in[8];
    const float* Wc1  = (const float*)d_in[9];
    const float* bc1  = (const float*)d_in[10];
    const float* Wc2  = (const float*)d_in[11];
    const float* bc2  = (const float*)d_in[12];
    float* out = (float*)d_out;

    cudaLaunchAttribute pdl_attr[1];
    pdl_attr[0].id = cudaLaunchAttributeProgrammaticStreamSerialization;
    pdl_attr[0].val.programmaticStreamSerializationAllowed = 1;

    // K1 (no predecessor)
    k_prep<<<148, 128>>>(traj, W1, b1, W2, b2, Wc1);

    // K2 with PDL on K1
    {
        cudaLaunchConfig_t cfg = {};
        cfg.gridDim = dim3(NN, 1, 1); cfg.blockDim = dim3(576, 1, 1);
        cfg.dynamicSmemBytes = 0; cfg.stream = 0;
        cfg.attrs = pdl_attr; cfg.numAttrs = 1;
        cudaLaunchKernelEx(&cfg, k_traj2, bc1, Wc2, bc2);
    }
    // K3 with PDL on K2: x-load + psm-halo phase overlaps the whole traj chain
    {
        cudaLaunchConfig_t cfg = {};
        cfg.gridDim = dim3(HW/32, BB, 1); cfg.blockDim = dim3(256, 1, 1);
        cfg.dynamicSmemBytes = 0; cfg.stream = 0;
        cfg.attrs = pdl_attr; cfg.numAttrs = 1;
        cudaLaunchKernelEx(&cfg, k_fuse, x, psm, out);
    }
}

// round 16
// speedup vs baseline: 1.0927x; 1.0927x over previous
#include <cuda_runtime.h>
#include <math.h>

#define BB 4
#define LL 5
#define TT 10
#define CC 64
#define HH 100
#define WW 352
#define NN (BB*LL)
#define HW (HH*WW)
#define H4 25
#define W4 88
#define P4 (H4*W4)

// PDL: let dependents launch early; wait = predecessor grid fully complete + visible
#define PDL_TRIGGER() asm volatile("griddepcontrol.launch_dependents;" ::: "memory")
#define PDL_WAIT()    asm volatile("griddepcontrol.wait;" ::: "memory")

// scratch (no allocations allowed)
__device__ float g_tm4[NN*P4];
__device__ float g_has[NN];
__device__ unsigned char g_mask[NN*HW];
__device__ float g_f[NN*128];
__device__ float g_R[9*128*64];       // conv weights pre-reduced to 9 border cases
__device__ int   g_xi[NN*TT], g_yi[NN*TT];
__device__ int   g_done[NN];          // per-agent intra-kernel flag (reset by k_prep)

// fast sigmoid via tanh.approx (mask path only -- feeds a 0.01 threshold, never the output values)
__device__ __forceinline__ float fast_sigmoid(float xv) {
    float t;
    asm("tanh.approx.f32 %0, %1;" : "=f"(t) : "f"(xv*0.5f));
    return fmaf(t, 0.5f, 0.5f);
}

// 5x5 gaussian, sigma=1, scaled by 1/(2*pi*sigma)
__constant__ float c_G[25] = {
    0.0029150244947655228f, 0.013064233284684921f, 0.021539279301848634f, 0.013064233284684921f, 0.0029150244947655228f,
    0.013064233284684921f, 0.05854983152431917f, 0.09653235263005391f, 0.05854983152431917f, 0.013064233284684921f,
    0.021539279301848634f, 0.09653235263005391f, 0.15915494309189535f, 0.09653235263005391f, 0.021539279301848634f,
    0.013064233284684921f, 0.05854983152431917f, 0.09653235263005391f, 0.05854983152431917f, 0.013064233284684921f,
    0.0029150244947655228f, 0.013064233284684921f, 0.021539279301848634f, 0.013064233284684921f, 0.0029150244947655228f
};

// 7x7 splat table: exp(-(di^2+dj^2)/8), di,dj in [-3,3]
__constant__ float c_g7[49] = {
    0.10539922456186433f, 0.19689917292530676f, 0.2865047968601901f, 0.32465246735834974f, 0.2865047968601901f, 0.19689917292530676f, 0.10539922456186433f,
    0.19689917292530676f, 0.36787944117144233f, 0.5352614285189903f, 0.6065306597126334f, 0.5352614285189903f, 0.36787944117144233f, 0.19689917292530676f,
    0.2865047968601901f, 0.5352614285189903f, 0.7788007830714049f, 0.8824969025845955f, 0.7788007830714049f, 0.5352614285189903f, 0.2865047968601901f,
    0.32465246735834974f, 0.6065306597126334f, 0.8824969025845955f, 1.0f, 0.8824969025845955f, 0.6065306597126334f, 0.32465246735834974f,
    0.2865047968601901f, 0.5352614285189903f, 0.7788007830714049f, 0.8824969025845955f, 0.7788007830714049f, 0.5352614285189903f, 0.2865047968601901f,
    0.19689917292530676f, 0.36787944117144233f, 0.5352614285189903f, 0.6065306597126334f, 0.5352614285189903f, 0.36787944117144233f, 0.19689917292530676f,
    0.10539922456186433f, 0.19689917292530676f, 0.2865047968601901f, 0.32465246735834974f, 0.2865047968601901f, 0.19689917292530676f, 0.10539922456186433f
};

// ---------------- K1: prep. Blocks 0..127: reduce Wc1 -> R. Blocks 128..147: per-agent MLP + flag reset ----------------
__global__ void __launch_bounds__(128)
k_prep(const float* __restrict__ traj_all,
       const float* __restrict__ W1, const float* __restrict__ b1,
       const float* __restrict__ W2, const float* __restrict__ b2,
       const float* __restrict__ Wc1)
{
    PDL_TRIGGER();
    int bid = blockIdx.x;
    int tid = threadIdx.x;

    if (bid < 128) {
        if (tid < 64) {
            int k = bid, o = tid;
            const float* w = Wc1 + (size_t)o*1152 + k*9;
            float w00=w[0], w01=w[1], w02=w[2];
            float w10=w[3], w11=w[4], w12=w[5];
            float w20=w[6], w21=w[7], w22=w[8];
            float rF0=w00+w01+w02, rL0=w01+w02, rR0=w00+w01;
            float rF1=w10+w11+w12, rL1=w11+w12, rR1=w10+w11;
            float rF2=w20+w21+w22, rL2=w21+w22, rR2=w20+w21;
            g_R[(0*128+k)*64+o]=rL1+rL2; g_R[(1*128+k)*64+o]=rF1+rF2; g_R[(2*128+k)*64+o]=rR1+rR2;
            g_R[(3*128+k)*64+o]=rL0+rL1+rL2; g_R[(4*128+k)*64+o]=rF0+rF1+rF2; g_R[(5*128+k)*64+o]=rR0+rR1+rR2;
            g_R[(6*128+k)*64+o]=rL0+rL1; g_R[(7*128+k)*64+o]=rF0+rF1; g_R[(8*128+k)*64+o]=rR0+rR1;
        }
        return;
    }

    int n = bid - 128;
    __shared__ float s_tr[TT*3];
    __shared__ float s_h[64];
    if (tid < TT*3) s_tr[tid] = traj_all[n*TT*3 + tid];
    __syncthreads();

    if (tid == 0) {
        g_done[n] = 0;                 // reset intra-kernel flag for this replay
        int h = 0;
        for (int i = 0; i < TT*3; i++) if (s_tr[i] != 0.0f) h = 1;
        g_has[n] = (float)h;
    }
    if (tid < TT) {
        float px = s_tr[tid*3+0] / 0.4f;     // DISCRETE_RATIO
        float py = s_tr[tid*3+1] / 0.4f;
        int xi = (int)(px / 4.0f);           // truncation like .astype(int32)
        int yi = (int)(py / 4.0f);
        g_xi[n*TT+tid] = min(max(xi, 0), W4-1);
        g_yi[n*TT+tid] = min(max(yi, 0), H4-1);
    }
    if (tid < 64) {
        float acc = 0.0f;
        #pragma unroll
        for (int t = 0; t < TT; t++) {
            float z = b1[tid];
            z += s_tr[t*3+0]*W1[0*64+tid];
            z += s_tr[t*3+1]*W1[1*64+tid];
            z += s_tr[t*3+2]*W1[2*64+tid];
            acc += fmaxf(z, 0.0f);
        }
        s_h[tid] = acc * 0.1f;
    }
    __syncthreads();
    {
        float z = b2[tid];
        #pragma unroll 8
        for (int c = 0; c < 64; c++) z += s_h[c]*W2[c*128+tid];
        g_f[n*128+tid] = z;
    }
}

// ---------------- K2: traj2 + cmask merged via per-agent flag ----------------
// Blocks 0..19: per-agent attention(9 cases) + table splat + normalize -> g_tm4, then flag.
// Blocks 20..1559: per-tile cmap + 5x5 smooth + threshold, spinning on the agent flag.
#define TILES_X 11
#define TILES_Y 7
#define TILES_PER_AGENT (TILES_X*TILES_Y)   // 77

__global__ void __launch_bounds__(576)
k_trajmask(const float* __restrict__ bc1, const float* __restrict__ Wc2,
           const float* __restrict__ bc2, const float* __restrict__ psm)
{
    PDL_TRIGGER();
    int bid = blockIdx.x;
    int tid = threadIdx.x;

    if (bid < NN) {
        // ======== traj2 body (R12) ========
        int n = bid;
        __shared__ float s_f[128];
        __shared__ float s_a9[9];
        __shared__ float s_red[9][2];
        __shared__ int   s_xi[TT], s_yi[TT];
        __shared__ float s_g7[49];
        __shared__ float s_m[P4];
        __shared__ float s_wsum[18];

        if (tid >= 128 && tid < 128+49) s_g7[tid-128] = c_g7[tid-128];  // independent prelude
        PDL_WAIT();   // g_f/g_xi/g_R/g_done-reset ready
        if (tid < 128) s_f[tid] = g_f[n*128+tid];
        if (tid < TT) { s_xi[tid] = g_xi[n*TT+tid]; s_yi[tid] = g_yi[n*TT+tid]; }
        __syncthreads();

        {
            int q = tid / 64, o = tid & 63;
            float acc = bc1[o];
            const float* Rp = g_R + (size_t)q*128*64 + o;
            #pragma unroll 8
            for (int k = 0; k < 128; k++) acc += s_f[k] * Rp[(size_t)k*64];
            float t = Wc2[o] * fmaxf(acc, 0.0f);
            #pragma unroll
            for (int off = 16; off > 0; off >>= 1)
                t += __shfl_down_sync(0xFFFFFFFFu, t, off);
            if ((tid & 31) == 0) s_red[q][(tid >> 5) & 1] = t;
        }
        __syncthreads();
        if (tid < 9) {
            float z = bc2[0] + s_red[tid][0] + s_red[tid][1];
            s_a9[tid] = fast_sigmoid(z);
        }
        __syncthreads();

        float lsum = 0.0f;
        for (int p = tid; p < P4; p += 576) {
            int i = p / W4, j = p - (p / W4)*W4;
            float m = 0.0f;
            #pragma unroll
            for (int t = 0; t < TT; t++) {
                int di = i - s_yi[t] + 3, dj = j - s_xi[t] + 3;
                if ((unsigned)di < 7u && (unsigned)dj < 7u) m += s_g7[di*7+dj];
            }
            s_m[p] = m; lsum += m;
        }
        #pragma unroll
        for (int off = 16; off > 0; off >>= 1)
            lsum += __shfl_down_sync(0xFFFFFFFFu, lsum, off);
        if ((tid & 31) == 0) s_wsum[tid >> 5] = lsum;
        __syncthreads();
        if (tid == 0) {
            float t = 0.0f;
            #pragma unroll
            for (int w = 0; w < 18; w++) t += s_wsum[w];
            s_wsum[0] = 1.0f / fmaxf(t, 1e-12f);
        }
        __syncthreads();
        float inv = s_wsum[0];
        for (int p = tid; p < P4; p += 576) {
            int i = p / W4, j = p - (p / W4)*W4;
            int r  = (i == 0) ? 0 : ((i == H4-1) ? 2 : 1);
            int cc = (j == 0) ? 0 : ((j == W4-1) ? 2 : 1);
            g_tm4[n*P4 + p] = s_m[p]*inv*s_a9[r*3+cc];
        }
        // publish
        __syncthreads();
        __threadfence();
        if (tid == 0) atomicExch(&g_done[n], 1);
        return;
    }

    // ======== cmask body (R12, 576 threads) ========
    {
        __shared__ float s_c[20][36];
        int t  = bid - NN;
        int n  = t / TILES_PER_AGENT;
        int rem = t - n*TILES_PER_AGENT;
        int bx = (rem % TILES_X) * 32;
        int by = (rem / TILES_X) * 16;

        PDL_WAIT();   // ensures g_done reset + g_has visible
        if (tid == 0) {
            volatile int* f = &g_done[n];
            while (*f == 0) { }
        }
        __syncthreads();
        __threadfence();

        const float* tmn = g_tm4 + n*P4;
        float has = g_has[n];

        for (int i = tid; i < 20*36; i += 576) {
            int ly = i / 36, lx = i - ly*36;
            int gx = bx + lx - 2, gy = by + ly - 2;
            float val = 0.0f;
            if (gx >= 0 && gx < WW && gy >= 0 && gy < HH) {
                float uy = fminf(fmaxf((gy+0.5f)*0.25f - 0.5f, 0.0f), (float)(H4-1));
                float ux = fminf(fmaxf((gx+0.5f)*0.25f - 0.5f, 0.0f), (float)(W4-1));
                int y0 = (int)uy, x0 = (int)ux;
                float fy = uy - y0, fx = ux - x0;
                int y1 = min(y0+1, H4-1), x1 = min(x0+1, W4-1);
                float v00 = tmn[y0*W4+x0], v01 = tmn[y0*W4+x1];
                float v10 = tmn[y1*W4+x0], v11 = tmn[y1*W4+x1];
                float tm = v00*(1.0f-fy)*(1.0f-fx) + v01*(1.0f-fy)*fx
                         + v10*fy*(1.0f-fx)        + v11*fy*fx;
                float fac = 1.0f + has*tm;
                int p = gy*WW + gx;
                float c0 = fast_sigmoid(psm[(size_t)(n*2+0)*HW + p]*fac);
                float c1 = fast_sigmoid(psm[(size_t)(n*2+1)*HW + p]*fac);
                val = fmaxf(c0, c1);
            }
            s_c[ly][lx] = val;
        }
        __syncthreads();

        if (tid < 512) {
            int lx = tid & 31, ly = tid >> 5;   // ly 0..15
            int gx = bx + lx, gy = by + ly;
            if (gy < HH) {
                float acc = 0.0f;
                #pragma unroll
                for (int dy = 0; dy < 5; dy++) {
                    #pragma unroll
                    for (int dx = 0; dx < 5; dx++)
                        acc += c_G[dy*5+dx] * s_c[ly+dy][lx+dx];
                }
                int l = n % LL;
                g_mask[(size_t)n*HW + gy*WW + gx] = (l == 0) ? 1 : ((acc > 0.01f) ? 1 : 0);
            }
        }
    }
}

// ---------------- K3: masked ego-row attention fusion (PDL two-phase, R12) ----------------
__global__ void __launch_bounds__(256)
k_fuse(const float* __restrict__ x, float* __restrict__ out)
{
    __shared__ float s_d[8][5][32];

    int px = threadIdx.x & 31;
    int cg = threadIdx.x >> 5;        // 0..7
    int p  = blockIdx.x * 32 + px;    // HW = 35200 = 1100 * 32
    int b  = blockIdx.y;

    const float* xb = x + (size_t)b*LL*CC*HW + p;

    // ---- phase 1: raw loads + raw dots (overlaps the mask-producing chain) ----
    float v[LL][8];
    #pragma unroll
    for (int m = 0; m < LL; m++) {
        #pragma unroll
        for (int i = 0; i < 8; i++)
            v[m][i] = xb[(size_t)(m*CC + cg*8 + i)*HW];
    }

    float d[LL];
    #pragma unroll
    for (int m = 0; m < LL; m++) d[m] = 0.0f;
    #pragma unroll
    for (int i = 0; i < 8; i++) {
        #pragma unroll
        for (int m = 0; m < LL; m++) d[m] += v[0][i]*v[m][i];
    }
    #pragma unroll
    for (int m = 0; m < LL; m++) s_d[cg][m][px] = d[m];
    __syncthreads();

    // ---- phase 2: need the mask now ----
    PDL_WAIT();
    float mk[LL];
    #pragma unroll
    for (int m = 0; m < LL; m++)
        mk[m] = (float)g_mask[(size_t)(b*LL+m)*HW + p];

    float e[LL], sum = 0.0f;
    #pragma unroll
    for (int m = 0; m < LL; m++) {
        float acc = 0.0f;
        #pragma unroll
        for (int g = 0; g < 8; g++) acc += s_d[g][m][px];
        e[m] = __expf(acc * mk[m] * 0.125f);   // mk in {0,1}, mk[0]==1; bounded exponent
        sum += e[m];
    }
    float isum = 1.0f/sum;

    float* ob = out + (size_t)b*CC*HW + p;
    #pragma unroll
    for (int i = 0; i < 8; i++) {
        float acc = e[0]*v[0][i]*mk[0] + e[1]*v[1][i]*mk[1] + e[2]*v[2][i]*mk[2]
                  + e[3]*v[3][i]*mk[3] + e[4]*v[4][i]*mk[4];
        ob[(size_t)(cg*8+i)*HW] = acc * isum;
    }
}

extern "C" void kernel_launch(void* const* d_in, const int* in_sizes, int n_in,
                              void* d_out, int out_size)
{
    const float* x    = (const float*)d_in[0];
    const float* psm  = (const float*)d_in[1];
    // d_in[2] record_len, d_in[3] pairwise_t_matrix: unused by reference
    const float* traj = (const float*)d_in[4];
    const float* W1   = (const float*)d_in[5];
    const float* b1   = (const float*)d_in[6];
    const float* W2   = (const float*)d_in[7];
    const float* b2   = (const float*)d_in[8];
    const float* Wc1  = (const float*)d_in[9];
    const float* bc1  = (const float*)d_in[10];
    const float* Wc2  = (const float*)d_in[11];
    const float* bc2  = (const float*)d_in[12];
    float* out = (float*)d_out;

    cudaLaunchAttribute pdl_attr[1];
    pdl_attr[0].id = cudaLaunchAttributeProgrammaticStreamSerialization;
    pdl_attr[0].val.programmaticStreamSerializationAllowed = 1;

    // K1 (no predecessor)
    k_prep<<<148, 128>>>(traj, W1, b1, W2, b2, Wc1);

    // K2 with PDL on K1: traj2 + cmask merged (intra-kernel per-agent flag)
    {
        cudaLaunchConfig_t cfg = {};
        cfg.gridDim = dim3(NN + NN*TILES_PER_AGENT, 1, 1);   // 20 + 1540
        cfg.blockDim = dim3(576, 1, 1);
        cfg.dynamicSmemBytes = 0; cfg.stream = 0;
        cfg.attrs = pdl_attr; cfg.numAttrs = 1;
        cudaLaunchKernelEx(&cfg, k_trajmask, bc1, Wc2, bc2, psm);
    }
    // K3 with PDL on K2: big x-load phase overlaps the whole mask chain
    {
        cudaLaunchConfig_t cfg = {};
        cfg.gridDim = dim3(HW/32, BB, 1); cfg.blockDim = dim3(256, 1, 1);
        cfg.dynamicSmemBytes = 0; cfg.stream = 0;
        cfg.attrs = pdl_attr; cfg.numAttrs = 1;
        cudaLaunchKernelEx(&cfg, k_fuse, x, out);
    }
}

// round 17
// speedup vs baseline: 1.2095x; 1.1069x over previous
#include <cuda_runtime.h>
#include <math.h>

#define BB 4
#define LL 5
#define TT 10
#define CC 64
#define HH 100
#define WW 352
#define NN (BB*LL)
#define HW (HH*WW)
#define H4 25
#define W4 88
#define P4 (H4*W4)

// PDL: let dependents launch early; wait = predecessor grid fully complete + visible
#define PDL_TRIGGER() asm volatile("griddepcontrol.launch_dependents;" ::: "memory")
#define PDL_WAIT()    asm volatile("griddepcontrol.wait;" ::: "memory")

// scratch (no allocations allowed)
__device__ float g_tm4[NN*P4];
__device__ float g_has[NN];
__device__ unsigned char g_mask[NN*HW];
__device__ float g_R[9*128*64];       // conv weights pre-reduced to 9 border cases
__device__ int   g_rdone = 0;         // R-fold producer counter (reset by k_fuse post-wait)

// fast sigmoid via tanh.approx (mask path only -- feeds a 0.01 threshold, never the output values)
__device__ __forceinline__ float fast_sigmoid(float xv) {
    float t;
    asm("tanh.approx.f32 %0, %1;" : "=f"(t) : "f"(xv*0.5f));
    return fmaf(t, 0.5f, 0.5f);
}

// 5x5 gaussian, sigma=1, scaled by 1/(2*pi*sigma)
__constant__ float c_G[25] = {
    0.0029150244947655228f, 0.013064233284684921f, 0.021539279301848634f, 0.013064233284684921f, 0.0029150244947655228f,
    0.013064233284684921f, 0.05854983152431917f, 0.09653235263005391f, 0.05854983152431917f, 0.013064233284684921f,
    0.021539279301848634f, 0.09653235263005391f, 0.15915494309189535f, 0.09653235263005391f, 0.021539279301848634f,
    0.013064233284684921f, 0.05854983152431917f, 0.09653235263005391f, 0.05854983152431917f, 0.013064233284684921f,
    0.0029150244947655228f, 0.013064233284684921f, 0.021539279301848634f, 0.013064233284684921f, 0.0029150244947655228f
};

// 7x7 splat table: exp(-(di^2+dj^2)/8), di,dj in [-3,3]
__constant__ float c_g7[49] = {
    0.10539922456186433f, 0.19689917292530676f, 0.2865047968601901f, 0.32465246735834974f, 0.2865047968601901f, 0.19689917292530676f, 0.10539922456186433f,
    0.19689917292530676f, 0.36787944117144233f, 0.5352614285189903f, 0.6065306597126334f, 0.5352614285189903f, 0.36787944117144233f, 0.19689917292530676f,
    0.2865047968601901f, 0.5352614285189903f, 0.7788007830714049f, 0.8824969025845955f, 0.7788007830714049f, 0.5352614285189903f, 0.2865047968601901f,
    0.32465246735834974f, 0.6065306597126334f, 0.8824969025845955f, 1.0f, 0.8824969025845955f, 0.6065306597126334f, 0.32465246735834974f,
    0.2865047968601901f, 0.5352614285189903f, 0.7788007830714049f, 0.8824969025845955f, 0.7788007830714049f, 0.5352614285189903f, 0.2865047968601901f,
    0.19689917292530676f, 0.36787944117144233f, 0.5352614285189903f, 0.6065306597126334f, 0.5352614285189903f, 0.36787944117144233f, 0.19689917292530676f,
    0.10539922456186433f, 0.19689917292530676f, 0.2865047968601901f, 0.32465246735834974f, 0.2865047968601901f, 0.19689917292530676f, 0.10539922456186433f
};

// ---------------- K1: R-fold (blocks 0..127) + full per-agent traj chain (blocks 128..147) ----------------
// 148 blocks, 1 per SM, all coresident -> waiter spin on g_rdone is deadlock-free.
__global__ void __launch_bounds__(576)
k_traj(const float* __restrict__ traj_all,
       const float* __restrict__ W1, const float* __restrict__ b1,
       const float* __restrict__ W2, const float* __restrict__ b2,
       const float* __restrict__ Wc1, const float* __restrict__ bc1,
       const float* __restrict__ Wc2, const float* __restrict__ bc2)
{
    PDL_TRIGGER();
    int bid = blockIdx.x;
    int tid = threadIdx.x;

    if (bid < 128) {
        // R[q][k=bid][o]: 576 threads = 9 q x 64 o, each folds its 3x3 border case
        int q = tid / 64, o = tid & 63;
        const float* w = Wc1 + (size_t)o*1152 + bid*9;
        float w00=w[0], w01=w[1], w02=w[2];
        float w10=w[3], w11=w[4], w12=w[5];
        float w20=w[6], w21=w[7], w22=w[8];
        int rowc = q / 3, colc = q - rowc*3;
        float s0 = (colc==0) ? (w01+w02) : ((colc==2) ? (w00+w01) : (w00+w01+w02));
        float s1 = (colc==0) ? (w11+w12) : ((colc==2) ? (w10+w11) : (w10+w11+w12));
        float s2 = (colc==0) ? (w21+w22) : ((colc==2) ? (w20+w21) : (w20+w21+w22));
        float val = (rowc==0) ? (s1+s2) : ((rowc==2) ? (s0+s1) : (s0+s1+s2));
        g_R[(q*128+bid)*64+o] = val;
        __syncthreads();
        __threadfence();
        if (tid == 0) atomicAdd(&g_rdone, 1);
        return;
    }

    // ---- per-agent chain: MLP (local) -> wait R -> GEMM -> a9 -> splat -> normalize ----
    int n = bid - 128;
    __shared__ float s_tr[TT*3];
    __shared__ float s_h[64];
    __shared__ float s_f[128];
    __shared__ float s_a9[9];
    __shared__ float s_red[9][2];
    __shared__ int   s_xi[TT], s_yi[TT];
    __shared__ float s_g7[49];
    __shared__ float s_m[P4];
    __shared__ float s_wsum[18];

    if (tid < TT*3) s_tr[tid] = traj_all[n*TT*3 + tid];
    if (tid >= 64 && tid < 64+49) s_g7[tid-64] = c_g7[tid-64];
    __syncthreads();

    if (tid == 0) {
        int h = 0;
        for (int i = 0; i < TT*3; i++) if (s_tr[i] != 0.0f) h = 1;
        g_has[n] = (float)h;
    }
    if (tid < TT) {
        float px = s_tr[tid*3+0] / 0.4f;     // DISCRETE_RATIO
        float py = s_tr[tid*3+1] / 0.4f;
        int xi = (int)(px / 4.0f);           // truncation like .astype(int32)
        int yi = (int)(py / 4.0f);
        s_xi[tid] = min(max(xi, 0), W4-1);
        s_yi[tid] = min(max(yi, 0), H4-1);
    }
    if (tid < 64) {
        float acc = 0.0f;
        #pragma unroll
        for (int t = 0; t < TT; t++) {
            float z = b1[tid];
            z += s_tr[t*3+0]*W1[0*64+tid];
            z += s_tr[t*3+1]*W1[1*64+tid];
            z += s_tr[t*3+2]*W1[2*64+tid];
            acc += fmaxf(z, 0.0f);
        }
        s_h[tid] = acc * 0.1f;
    }
    __syncthreads();
    if (tid < 128) {
        float z = b2[tid];
        #pragma unroll 8
        for (int c = 0; c < 64; c++) z += s_h[c]*W2[c*128+tid];
        s_f[tid] = z;
    }

    // wait for all 128 R-fold producers (all coresident: no deadlock)
    if (tid == 0) {
        volatile int* f = &g_rdone;
        while (*f < 128) { }
    }
    __syncthreads();
    __threadfence();

    {
        int q = tid / 64, o = tid & 63;
        float acc = bc1[o];
        const float* Rp = g_R + (size_t)q*128*64 + o;
        #pragma unroll 8
        for (int k = 0; k < 128; k++) acc += s_f[k] * Rp[(size_t)k*64];
        float t = Wc2[o] * fmaxf(acc, 0.0f);
        #pragma unroll
        for (int off = 16; off > 0; off >>= 1)
            t += __shfl_down_sync(0xFFFFFFFFu, t, off);
        if ((tid & 31) == 0) s_red[q][(tid >> 5) & 1] = t;
    }
    __syncthreads();
    if (tid < 9) {
        float z = bc2[0] + s_red[tid][0] + s_red[tid][1];
        s_a9[tid] = fast_sigmoid(z);
    }
    __syncthreads();

    float lsum = 0.0f;
    for (int p = tid; p < P4; p += 576) {
        int i = p / W4, j = p - (p / W4)*W4;
        float m = 0.0f;
        #pragma unroll
        for (int t = 0; t < TT; t++) {
            int di = i - s_yi[t] + 3, dj = j - s_xi[t] + 3;
            if ((unsigned)di < 7u && (unsigned)dj < 7u) m += s_g7[di*7+dj];
        }
        s_m[p] = m; lsum += m;
    }
    #pragma unroll
    for (int off = 16; off > 0; off >>= 1)
        lsum += __shfl_down_sync(0xFFFFFFFFu, lsum, off);
    if ((tid & 31) == 0) s_wsum[tid >> 5] = lsum;
    __syncthreads();
    if (tid == 0) {
        float t = 0.0f;
        #pragma unroll
        for (int w = 0; w < 18; w++) t += s_wsum[w];
        s_wsum[0] = 1.0f / fmaxf(t, 1e-12f);
    }
    __syncthreads();
    float inv = s_wsum[0];
    for (int p = tid; p < P4; p += 576) {
        int i = p / W4, j = p - (p / W4)*W4;
        int r  = (i == 0) ? 0 : ((i == H4-1) ? 2 : 1);
        int cc = (j == 0) ? 0 : ((j == W4-1) ? 2 : 1);
        g_tm4[n*P4 + p] = s_m[p]*inv*s_a9[r*3+cc];
    }
}

// ---------------- K2: fused cmap + 5x5 smooth + threshold + ego force ----------------
// Tile 32x16, halo 2. tm4 bilinear window (6x10) staged in smem: LDS instead of scattered L2.
__global__ void __launch_bounds__(256)
k_cmask(const float* __restrict__ psm)
{
    PDL_TRIGGER();
    __shared__ float s_t[6][10];
    __shared__ float s_c[20][36];
    int n  = blockIdx.z;
    int bx = blockIdx.x * 32;
    int by = blockIdx.y * 16;
    int tid = threadIdx.x;

    PDL_WAIT();   // g_tm4/g_has ready
    const float* tmn = g_tm4 + n*P4;
    float has = g_has[n];

    int tyb = by/4 - 1, txb = bx/4 - 1;
    if (tid < 60) {
        int r = tid / 10, c = tid - r*10;
        int gy = min(max(tyb + r, 0), H4-1);
        int gx = min(max(txb + c, 0), W4-1);
        s_t[r][c] = tmn[gy*W4 + gx];
    }
    __syncthreads();

    for (int i = tid; i < 20*36; i += 256) {
        int ly = i / 36, lx = i - ly*36;
        int gx = bx + lx - 2, gy = by + ly - 2;
        float val = 0.0f;
        if (gx >= 0 && gx < WW && gy >= 0 && gy < HH) {
            float uy = fminf(fmaxf((gy+0.5f)*0.25f - 0.5f, 0.0f), (float)(H4-1));
            float ux = fminf(fmaxf((gx+0.5f)*0.25f - 0.5f, 0.0f), (float)(W4-1));
            int y0 = (int)uy, x0 = (int)ux;
            float fy = uy - y0, fx = ux - x0;
            int y1 = min(y0+1, H4-1), x1 = min(x0+1, W4-1);
            int ly0 = y0 - tyb, ly1 = y1 - tyb;
            int lx0 = x0 - txb, lx1 = x1 - txb;
            float v00 = s_t[ly0][lx0], v01 = s_t[ly0][lx1];
            float v10 = s_t[ly1][lx0], v11 = s_t[ly1][lx1];
            float tm = v00*(1.0f-fy)*(1.0f-fx) + v01*(1.0f-fy)*fx
                     + v10*fy*(1.0f-fx)        + v11*fy*fx;
            float fac = 1.0f + has*tm;
            int p = gy*WW + gx;
            float c0 = fast_sigmoid(psm[(size_t)(n*2+0)*HW + p]*fac);
            float c1 = fast_sigmoid(psm[(size_t)(n*2+1)*HW + p]*fac);
            val = fmaxf(c0, c1);
        }
        s_c[ly][lx] = val;
    }
    __syncthreads();

    int lx = tid & 31;
    int l  = n % LL;
    unsigned char* mb = g_mask + (size_t)n*HW;
    #pragma unroll
    for (int r = 0; r < 2; r++) {
        int ly = (tid >> 5) + r*8;
        int gx = bx + lx, gy = by + ly;
        if (gy < HH) {
            float acc = 0.0f;
            #pragma unroll
            for (int dy = 0; dy < 5; dy++) {
                #pragma unroll
                for (int dx = 0; dx < 5; dx++)
                    acc += c_G[dy*5+dx] * s_c[ly+dy][lx+dx];
            }
            mb[gy*WW + gx] = (l == 0) ? 1 : ((acc > 0.01f) ? 1 : 0);
        }
    }
}

// ---------------- K3: masked ego-row attention fusion (PDL two-phase, R12) ----------------
__global__ void __launch_bounds__(256)
k_fuse(const float* __restrict__ x, float* __restrict__ out)
{
    __shared__ float s_d[8][5][32];

    int px = threadIdx.x & 31;
    int cg = threadIdx.x >> 5;        // 0..7
    int p  = blockIdx.x * 32 + px;    // HW = 35200 = 1100 * 32
    int b  = blockIdx.y;

    const float* xb = x + (size_t)b*LL*CC*HW + p;

    // ---- phase 1: raw loads + raw dots (overlaps the mask-producing chain) ----
    float v[LL][8];
    #pragma unroll
    for (int m = 0; m < LL; m++) {
        #pragma unroll
        for (int i = 0; i < 8; i++)
            v[m][i] = xb[(size_t)(m*CC + cg*8 + i)*HW];
    }

    float d[LL];
    #pragma unroll
    for (int m = 0; m < LL; m++) d[m] = 0.0f;
    #pragma unroll
    for (int i = 0; i < 8; i++) {
        #pragma unroll
        for (int m = 0; m < LL; m++) d[m] += v[0][i]*v[m][i];
    }
    #pragma unroll
    for (int m = 0; m < LL; m++) s_d[cg][m][px] = d[m];
    __syncthreads();

    // ---- phase 2: need the mask now ----
    PDL_WAIT();
    // reset the K1 producer counter for the NEXT stream-ordered replay.
    // Safe here: PDL_WAIT => cmask grid done => (cmask waited on K1) => K1 grid done.
    if (blockIdx.x == 0 && blockIdx.y == 0 && threadIdx.x == 0) g_rdone = 0;

    float mk[LL];
    #pragma unroll
    for (int m = 0; m < LL; m++)
        mk[m] = (float)g_mask[(size_t)(b*LL+m)*HW + p];

    float e[LL], sum = 0.0f;
    #pragma unroll
    for (int m = 0; m < LL; m++) {
        float acc = 0.0f;
        #pragma unroll
        for (int g = 0; g < 8; g++) acc += s_d[g][m][px];
        e[m] = __expf(acc * mk[m] * 0.125f);   // mk in {0,1}, mk[0]==1; bounded exponent
        sum += e[m];
    }
    float isum = 1.0f/sum;

    float* ob = out + (size_t)b*CC*HW + p;
    #pragma unroll
    for (int i = 0; i < 8; i++) {
        float acc = e[0]*v[0][i]*mk[0] + e[1]*v[1][i]*mk[1] + e[2]*v[2][i]*mk[2]
                  + e[3]*v[3][i]*mk[3] + e[4]*v[4][i]*mk[4];
        ob[(size_t)(cg*8+i)*HW] = acc * isum;
    }
}

extern "C" void kernel_launch(void* const* d_in, const int* in_sizes, int n_in,
                              void* d_out, int out_size)
{
    const float* x    = (const float*)d_in[0];
    const float* psm  = (const float*)d_in[1];
    // d_in[2] record_len, d_in[3] pairwise_t_matrix: unused by reference
    const float* traj = (const float*)d_in[4];
    const float* W1   = (const float*)d_in[5];
    const float* b1   = (const float*)d_in[6];
    const float* W2   = (const float*)d_in[7];
    const float* b2   = (const float*)d_in[8];
    const float* Wc1  = (const float*)d_in[9];
    const float* bc1  = (const float*)d_in[10];
    const float* Wc2  = (const float*)d_in[11];
    const float* bc2  = (const float*)d_in[12];
    float* out = (float*)d_out;

    cudaLaunchAttribute pdl_attr[1];
    pdl_attr[0].id = cudaLaunchAttributeProgrammaticStreamSerialization;
    pdl_attr[0].val.programmaticStreamSerializationAllowed = 1;

    // K1 (no predecessor): R-fold + traj chain, 148 blocks (one per SM)
    k_traj<<<148, 576>>>(traj, W1, b1, W2, b2, Wc1, bc1, Wc2, bc2);

    // K2 with PDL on K1
    {
        cudaLaunchConfig_t cfg = {};
        cfg.gridDim = dim3(WW/32, (HH+15)/16, NN); cfg.blockDim = dim3(256, 1, 1);
        cfg.dynamicSmemBytes = 0; cfg.stream = 0;
        cfg.attrs = pdl_attr; cfg.numAttrs = 1;
        cudaLaunchKernelEx(&cfg, k_cmask, psm);
    }
    // K3 with PDL on K2: big x-load phase overlaps the whole mask chain
    {
        cudaLaunchConfig_t cfg = {};
        cfg.gridDim = dim3(HW/32, BB, 1); cfg.blockDim = dim3(256, 1, 1);
        cfg.dynamicSmemBytes = 0; cfg.stream = 0;
        cfg.attrs = pdl_attr; cfg.numAttrs = 1;
        cudaLaunchKernelEx(&cfg, k_fuse, x, out);
    }
}